// round 9
// baseline (speedup 1.0000x reference)
#include <cuda_runtime.h>
#include <cuda_bf16.h>
#include <cstdint>

#define N_SAMP 256
#define IN_F   1024
#define B_F    128
#define C_F    16
#define J_F    (B_F * C_F)   // 2048
#define OUT_W  (IN_F + B_F)  // 1152

// ---------------- scratch (no allocs allowed) ----------------
__device__ float          g_mat[B_F * N_SAMP * C_F];   // [b][n][c] fp32, 2MB
__device__ __nv_bfloat16  g_xb[N_SAMP * IN_F];         // x bf16 [256][1024]
__device__ __nv_bfloat16  g_Tt[J_F * IN_F];            // T^T bf16 [2048][1024]

__device__ __forceinline__ uint32_t smem_u32(const void* p) {
    uint32_t a;
    asm("{ .reg .u64 t; cvta.to.shared.u64 t, %1; cvt.u32.u64 %0, t; }" : "=r"(a) : "l"(p));
    return a;
}

// ---------------------------------------------------------------------------
// prep: blocks [0,2048): transpose T fp32 [1024][2048] -> g_Tt bf16 [2048][1024]
//       blocks [2048,2304): x fp32 -> g_xb bf16 + copy x into out[:,0:1024]
// ---------------------------------------------------------------------------
__global__ __launch_bounds__(256) void prep_kernel(const float* __restrict__ x,
                                                   const float* __restrict__ T,
                                                   float* __restrict__ out) {
    __shared__ float s[32][33];
    const int tid = threadIdx.x;
    if (blockIdx.x < 2048) {
        const int tx = tid & 31, ty = tid >> 5;          // (32, 8)
        const int bj = (blockIdx.x & 63) * 32;
        const int bk = (blockIdx.x >> 6) * 32;
        #pragma unroll
        for (int i = 0; i < 4; i++)
            s[ty + i * 8][tx] = T[(bk + ty + i * 8) * J_F + bj + tx];
        __syncthreads();
        #pragma unroll
        for (int i = 0; i < 4; i++)
            g_Tt[(size_t)(bj + ty + i * 8) * IN_F + bk + tx] =
                __float2bfloat16(s[tx][ty + i * 8]);
    } else {
        int idx = (blockIdx.x - 2048) * 256 + tid;       // float4 index, 65536 total
        float4 v = ((const float4*)x)[idx];
        int n = idx >> 8, c4 = idx & 255;
        ((float4*)(out + n * OUT_W))[c4] = v;
        __nv_bfloat162* xb2 = (__nv_bfloat162*)g_xb;
        xb2[idx * 2 + 0] = __floats2bfloat162_rn(v.x, v.y);
        xb2[idx * 2 + 1] = __floats2bfloat162_rn(v.z, v.w);
    }
}

// ---------------------------------------------------------------------------
// mma.sync bf16 GEMM  (unchanged)
// ---------------------------------------------------------------------------
#define GBM 64
#define GBN 128
#define GBK 32
#define KITERS (IN_F / GBK)   // 32

__global__ __launch_bounds__(256, 1) void gemm_mma_kernel() {
    __shared__ __nv_bfloat16 As[2][GBM][40];
    __shared__ __nv_bfloat16 Bs[2][GBN][40];

    const int tid  = threadIdx.x;
    const int wid  = tid >> 5;
    const int lane = tid & 31;
    const int bn   = blockIdx.x;       // 0..15
    const int bm   = blockIdx.y;       // 0..3
    const int wm   = wid >> 2;         // 0..1
    const int wn   = wid & 3;          // 0..3

    const __nv_bfloat16* Ab = g_xb + (size_t)(bm * GBM) * IN_F;
    const __nv_bfloat16* Bb = g_Tt + (size_t)(bn * GBN) * IN_F;

    const int lrow = tid >> 2;         // 0..63
    const int lseg = (tid & 3) * 8;    // 0,8,16,24

    float acc[2][4][4] = {};

    {
        *(uint4*)&As[0][lrow][lseg] = *(const uint4*)(Ab + lrow * IN_F + lseg);
        *(uint4*)&Bs[0][lrow][lseg] = *(const uint4*)(Bb + lrow * IN_F + lseg);
        *(uint4*)&Bs[0][lrow + 64][lseg] = *(const uint4*)(Bb + (lrow + 64) * IN_F + lseg);
    }
    __syncthreads();

    for (int it = 0; it < KITERS; it++) {
        const int buf = it & 1;
        if (it + 1 < KITERS) {
            const int kt = (it + 1) * GBK;
            const int nb = buf ^ 1;
            *(uint4*)&As[nb][lrow][lseg] = *(const uint4*)(Ab + lrow * IN_F + kt + lseg);
            *(uint4*)&Bs[nb][lrow][lseg] = *(const uint4*)(Bb + lrow * IN_F + kt + lseg);
            *(uint4*)&Bs[nb][lrow + 64][lseg] = *(const uint4*)(Bb + (lrow + 64) * IN_F + kt + lseg);
        }

        #pragma unroll
        for (int ks = 0; ks < 2; ks++) {
            uint32_t a[2][4];
            const int sub  = lane >> 3;
            const int arow = (sub & 1) * 8 + (lane & 7);
            const int acol = ks * 16 + (sub >> 1) * 8;
            #pragma unroll
            for (int mf = 0; mf < 2; mf++) {
                uint32_t addr = smem_u32(&As[buf][wm * 32 + mf * 16 + arow][acol]);
                asm volatile("ldmatrix.sync.aligned.m8n8.x4.shared.b16 {%0,%1,%2,%3}, [%4];"
                             : "=r"(a[mf][0]), "=r"(a[mf][1]), "=r"(a[mf][2]), "=r"(a[mf][3])
                             : "r"(addr));
            }
            uint32_t b0[4], b1[4];
            #pragma unroll
            for (int nf = 0; nf < 4; nf++) {
                const __nv_bfloat16* p =
                    &Bs[buf][wn * 32 + nf * 8 + (lane >> 2)][ks * 16 + (lane & 3) * 2];
                b0[nf] = *(const uint32_t*)p;
                b1[nf] = *(const uint32_t*)(p + 8);
            }
            #pragma unroll
            for (int mf = 0; mf < 2; mf++)
                #pragma unroll
                for (int nf = 0; nf < 4; nf++)
                    asm volatile(
                        "mma.sync.aligned.m16n8k16.row.col.f32.bf16.bf16.f32 "
                        "{%0,%1,%2,%3}, {%4,%5,%6,%7}, {%8,%9}, {%0,%1,%2,%3};"
                        : "+f"(acc[mf][nf][0]), "+f"(acc[mf][nf][1]),
                          "+f"(acc[mf][nf][2]), "+f"(acc[mf][nf][3])
                        : "r"(a[mf][0]), "r"(a[mf][1]), "r"(a[mf][2]), "r"(a[mf][3]),
                          "r"(b0[nf]), "r"(b1[nf]));
        }
        __syncthreads();
    }

    const int g   = lane >> 2;
    const int cc  = (lane & 3) * 2;
    #pragma unroll
    for (int mf = 0; mf < 2; mf++) {
        const int row0 = bm * GBM + wm * 32 + mf * 16 + g;
        #pragma unroll
        for (int nf = 0; nf < 4; nf++) {
            const int j  = bn * GBN + wn * 32 + nf * 8 + cc;
            const int bb = j >> 4;
            const int c  = j & 15;
            float* dst = g_mat + bb * (N_SAMP * C_F);
            *(float2*)(dst + row0 * C_F + c) =
                make_float2(acc[mf][nf][0], acc[mf][nf][1]);
            *(float2*)(dst + (row0 + 8) * C_F + c) =
                make_float2(acc[mf][nf][2], acc[mf][nf][3]);
        }
    }
}

// ---------------------------------------------------------------------------
// Pairwise, v3: 8-group (2-channel) triangle-inequality bound, analytic self
// term, self excluded from the warp vote.
// grid (128 b, 2 n-halves), block 512 = 128 n x 4 m-quarters.
// Bound is an exact lower bound on d; pruned pairs have exp(-d) <= e^-40.
// ---------------------------------------------------------------------------
__global__ __launch_bounds__(512) void pair_kernel(float* __restrict__ out) {
    __shared__ float  sm[N_SAMP][C_F];      // 16 KB
    __shared__ float4 sg[N_SAMP][2];        // 8 KB: 8 group sums / row
    __shared__ float  red[3][128];          // quarter partials

    const int b   = blockIdx.x;
    const int tid = threadIdx.x;
    const float* mb = g_mat + b * (N_SAMP * C_F);

    #pragma unroll
    for (int r = 0; r < 2; r++) {
        int i = tid + r * 512;              // float4 index, 1024 total
        ((float4*)sm)[i] = ((const float4*)mb)[i];
    }
    __syncthreads();

    // group sums: thread t -> row t/2, half t&1 (4 groups of 2 channels)
    {
        const int r = tid >> 1, h = tid & 1;
        const float4 p = *(const float4*)&sm[r][h * 8];
        const float4 q = *(const float4*)&sm[r][h * 8 + 4];
        sg[r][h] = make_float4(p.x + p.y, p.z + p.w, q.x + q.y, q.z + q.w);
    }
    __syncthreads();

    const int nl = tid & 127;               // n lane within half
    const int q  = tid >> 7;                // m quarter 0..3
    const int n  = blockIdx.y * 128 + nl;

    const float4 a0 = *(const float4*)&sm[n][0];
    const float4 a1 = *(const float4*)&sm[n][4];
    const float4 a2 = *(const float4*)&sm[n][8];
    const float4 a3 = *(const float4*)&sm[n][12];
    const float4 mg0 = sg[n][0];
    const float4 mg1 = sg[n][1];

    float acc = 0.f;
    const int m0 = q * 64;
    #pragma unroll 4
    for (int m = m0; m < m0 + 64; m++) {
        const float4 g0 = sg[m][0];          // broadcast LDS.128
        const float4 g1 = sg[m][1];
        float bnd;
        bnd  = fabsf(mg0.x - g0.x) + fabsf(mg0.y - g0.y);
        bnd += fabsf(mg0.z - g0.z) + fabsf(mg0.w - g0.w);
        bnd += fabsf(mg1.x - g1.x) + fabsf(mg1.y - g1.y);
        bnd += fabsf(mg1.z - g1.z) + fabsf(mg1.w - g1.w);
        const bool hit = (bnd < 40.f) && (m != n);
        if (__any_sync(0xFFFFFFFFu, hit)) {
            const float4 v0 = *(const float4*)&sm[m][0];
            const float4 v1 = *(const float4*)&sm[m][4];
            const float4 v2 = *(const float4*)&sm[m][8];
            const float4 v3 = *(const float4*)&sm[m][12];
            float d = 0.f;
            d += fabsf(a0.x - v0.x); d += fabsf(a0.y - v0.y);
            d += fabsf(a0.z - v0.z); d += fabsf(a0.w - v0.w);
            d += fabsf(a1.x - v1.x); d += fabsf(a1.y - v1.y);
            d += fabsf(a1.z - v1.z); d += fabsf(a1.w - v1.w);
            d += fabsf(a2.x - v2.x); d += fabsf(a2.y - v2.y);
            d += fabsf(a2.z - v2.z); d += fabsf(a2.w - v2.w);
            d += fabsf(a3.x - v3.x); d += fabsf(a3.y - v3.y);
            d += fabsf(a3.z - v3.z); d += fabsf(a3.w - v3.w);
            if (m != n) acc += __expf(-d);   // d>=40 lanes underflow to 0
        }
    }

    if (q > 0) red[q - 1][nl] = acc;
    __syncthreads();
    if (q == 0)
        out[n * OUT_W + IN_F + b] =
            1.0f + acc + red[0][nl] + red[1][nl] + red[2][nl];  // +1 = self term
}

// ---------------------------------------------------------------------------
extern "C" void kernel_launch(void* const* d_in, const int* in_sizes, int n_in,
                              void* d_out, int out_size) {
    const float* x = (const float*)d_in[0];   // [256, 1024]
    const float* T = (const float*)d_in[1];   // [1024, 128, 16]
    float* out = (float*)d_out;               // [256, 1152]

    prep_kernel<<<2304, 256>>>(x, T, out);
    gemm_mma_kernel<<<dim3(J_F / GBN, N_SAMP / GBM), 256>>>();
    pair_kernel<<<dim3(B_F, 2), 512>>>(out);
}

// round 12
// speedup vs baseline: 1.4215x; 1.4215x over previous
#include <cuda_runtime.h>
#include <cuda_bf16.h>
#include <cstdint>

#define N_SAMP 256
#define IN_F   1024
#define B_F    128
#define C_F    16
#define J_F    (B_F * C_F)   // 2048
#define OUT_W  (IN_F + B_F)  // 1152

// ---------------- scratch (no allocs allowed) ----------------
__device__ float g_mat[B_F * N_SAMP * C_F];   // [b][n][c] fp32, 2MB

__device__ __forceinline__ uint32_t smem_u32(const void* p) {
    uint32_t a;
    asm("{ .reg .u64 t; cvta.to.shared.u64 t, %1; cvt.u32.u64 %0, t; }" : "=r"(a) : "l"(p));
    return a;
}

// ---------------------------------------------------------------------------
// copy x into out[:, 0:1024]
// ---------------------------------------------------------------------------
__global__ __launch_bounds__(256) void copy_kernel(const float* __restrict__ x,
                                                   float* __restrict__ out) {
    int idx = blockIdx.x * 256 + threadIdx.x;   // float4 index, 65536 total
    int n = idx >> 8, c4 = idx & 255;
    ((float4*)(out + n * OUT_W))[c4] = ((const float4*)(x + n * IN_F))[c4];
}

// ---------------------------------------------------------------------------
// Fused-convert bf16 MMA GEMM: g_mat scatter of C[n][j] = sum_k x[n][k]*T[k][j]
// Reads x, T fp32 directly; converts to bf16 while staging to SMEM.
// BM=BN=BK=64 -> grid (32,4) = 128 CTAs. 8 warps = 2(M) x 4(N), warp tile
// 32x16. A frag: ldmatrix.x4 from [m][k]; B frag: ldmatrix.x4.trans from
// [k][n] (handles the transpose in-flight). Rows padded to 72 bf16 (144B)
// -> conflict-free ldmatrix phases. Double-buffered.
// ---------------------------------------------------------------------------
#define BM 64
#define BN 64
#define BK 64
#define KIT (IN_F / BK)   // 16

__global__ __launch_bounds__(256, 1) void gemm_fused_kernel(const float* __restrict__ x,
                                                            const float* __restrict__ T) {
    __shared__ __align__(16) __nv_bfloat16 As[2][BM][BK + 8];  // [m][k] 18KB
    __shared__ __align__(16) __nv_bfloat16 Bs[2][BK][BN + 8];  // [k][n] 18KB

    const int tid  = threadIdx.x;
    const int wid  = tid >> 5;
    const int lane = tid & 31;
    const int bn   = blockIdx.x;     // 0..31
    const int bm   = blockIdx.y;     // 0..3
    const int wm   = wid >> 2;       // 0..1 -> m offset wm*32
    const int wn   = wid & 3;        // 0..3 -> n offset wn*16

    // staging map: 1024 float4 per tile per stage, 4 per thread
    // f4i -> row = f4i>>4 (0..63), seg = f4i&15 (fp32 col = seg*4)
    const float* Axb = x + (size_t)(bm * BM) * IN_F;
    const float* Tb  = T + bn * BN;

    auto stage = [&](int buf, int kt) {
        #pragma unroll
        for (int i = 0; i < 4; i++) {
            const int f4i = tid + i * 256;
            const int row = f4i >> 4, seg = f4i & 15;
            // A: x[bm*64+row][kt + seg*4]
            float4 va = *(const float4*)(Axb + (size_t)row * IN_F + kt + seg * 4);
            __nv_bfloat162 alo = __floats2bfloat162_rn(va.x, va.y);
            __nv_bfloat162 ahi = __floats2bfloat162_rn(va.z, va.w);
            *(uint2*)&As[buf][row][seg * 4] =
                make_uint2(*(uint32_t*)&alo, *(uint32_t*)&ahi);
            // B: T[kt+row][bn*64 + seg*4]
            float4 vb = *(const float4*)(Tb + (size_t)(kt + row) * J_F + seg * 4);
            __nv_bfloat162 blo = __floats2bfloat162_rn(vb.x, vb.y);
            __nv_bfloat162 bhi = __floats2bfloat162_rn(vb.z, vb.w);
            *(uint2*)&Bs[buf][row][seg * 4] =
                make_uint2(*(uint32_t*)&blo, *(uint32_t*)&bhi);
        }
    };

    float acc[2][2][4] = {};

    stage(0, 0);
    __syncthreads();

    for (int it = 0; it < KIT; it++) {
        const int buf = it & 1;
        if (it + 1 < KIT) stage(buf ^ 1, (it + 1) * BK);

        #pragma unroll
        for (int ks = 0; ks < 4; ks++) {
            // A fragments (non-trans x4), layout proven in R6
            uint32_t a[2][4];
            const int sub  = lane >> 3;
            const int arow = (sub & 1) * 8 + (lane & 7);
            const int acol = ks * 16 + (sub >> 1) * 8;
            #pragma unroll
            for (int mf = 0; mf < 2; mf++) {
                uint32_t addr = smem_u32(&As[buf][wm * 32 + mf * 16 + arow][acol]);
                asm volatile("ldmatrix.sync.aligned.m8n8.x4.shared.b16 {%0,%1,%2,%3}, [%4];"
                             : "=r"(a[mf][0]), "=r"(a[mf][1]), "=r"(a[mf][2]), "=r"(a[mf][3])
                             : "r"(addr));
            }
            // B fragment: x4.trans from [k][n] tile
            // t0-7: k0-7/n0-7 -> b0(nf0); t8-15: k8-15/n0-7 -> b1(nf0);
            // t16-23: k0-7/n8-15 -> b0(nf1); t24-31 -> b1(nf1)
            uint32_t b[4];
            {
                const int brow = ks * 16 + (lane & 15);
                const int bcol = wn * 16 + (lane >> 4) * 8;
                uint32_t addr = smem_u32(&Bs[buf][brow][bcol]);
                asm volatile("ldmatrix.sync.aligned.m8n8.x4.trans.shared.b16 {%0,%1,%2,%3}, [%4];"
                             : "=r"(b[0]), "=r"(b[1]), "=r"(b[2]), "=r"(b[3])
                             : "r"(addr));
            }
            #pragma unroll
            for (int mf = 0; mf < 2; mf++)
                #pragma unroll
                for (int nf = 0; nf < 2; nf++)
                    asm volatile(
                        "mma.sync.aligned.m16n8k16.row.col.f32.bf16.bf16.f32 "
                        "{%0,%1,%2,%3}, {%4,%5,%6,%7}, {%8,%9}, {%0,%1,%2,%3};"
                        : "+f"(acc[mf][nf][0]), "+f"(acc[mf][nf][1]),
                          "+f"(acc[mf][nf][2]), "+f"(acc[mf][nf][3])
                        : "r"(a[mf][0]), "r"(a[mf][1]), "r"(a[mf][2]), "r"(a[mf][3]),
                          "r"(b[nf * 2]), "r"(b[nf * 2 + 1]));
        }
        __syncthreads();
    }

    // Epilogue: scatter into g_mat[b][n][c], b = j>>4, c = j&15
    const int g  = lane >> 2;
    const int cc = (lane & 3) * 2;
    #pragma unroll
    for (int mf = 0; mf < 2; mf++) {
        const int row0 = bm * BM + wm * 32 + mf * 16 + g;
        #pragma unroll
        for (int nf = 0; nf < 2; nf++) {
            const int j  = bn * BN + wn * 16 + nf * 8 + cc;
            const int bb = j >> 4;
            const int c  = j & 15;
            float* dst = g_mat + bb * (N_SAMP * C_F);
            *(float2*)(dst + row0 * C_F + c) =
                make_float2(acc[mf][nf][0], acc[mf][nf][1]);
            *(float2*)(dst + (row0 + 8) * C_F + c) =
                make_float2(acc[mf][nf][2], acc[mf][nf][3]);
        }
    }
}

// ---------------------------------------------------------------------------
// Pairwise (unchanged from R9): 8-group triangle bound, analytic self term.
// grid (128 b, 2 n-halves), block 512 = 128 n x 4 m-quarters.
// ---------------------------------------------------------------------------
__global__ __launch_bounds__(512) void pair_kernel(float* __restrict__ out) {
    __shared__ float  sm[N_SAMP][C_F];      // 16 KB
    __shared__ float4 sg[N_SAMP][2];        // 8 KB
    __shared__ float  red[3][128];

    const int b   = blockIdx.x;
    const int tid = threadIdx.x;
    const float* mb = g_mat + b * (N_SAMP * C_F);

    #pragma unroll
    for (int r = 0; r < 2; r++) {
        int i = tid + r * 512;
        ((float4*)sm)[i] = ((const float4*)mb)[i];
    }
    __syncthreads();

    {
        const int r = tid >> 1, h = tid & 1;
        const float4 p = *(const float4*)&sm[r][h * 8];
        const float4 q = *(const float4*)&sm[r][h * 8 + 4];
        sg[r][h] = make_float4(p.x + p.y, p.z + p.w, q.x + q.y, q.z + q.w);
    }
    __syncthreads();

    const int nl = tid & 127;
    const int q  = tid >> 7;
    const int n  = blockIdx.y * 128 + nl;

    const float4 a0 = *(const float4*)&sm[n][0];
    const float4 a1 = *(const float4*)&sm[n][4];
    const float4 a2 = *(const float4*)&sm[n][8];
    const float4 a3 = *(const float4*)&sm[n][12];
    const float4 mg0 = sg[n][0];
    const float4 mg1 = sg[n][1];

    float acc = 0.f;
    const int m0 = q * 64;
    #pragma unroll 4
    for (int m = m0; m < m0 + 64; m++) {
        const float4 g0 = sg[m][0];
        const float4 g1 = sg[m][1];
        float bnd;
        bnd  = fabsf(mg0.x - g0.x) + fabsf(mg0.y - g0.y);
        bnd += fabsf(mg0.z - g0.z) + fabsf(mg0.w - g0.w);
        bnd += fabsf(mg1.x - g1.x) + fabsf(mg1.y - g1.y);
        bnd += fabsf(mg1.z - g1.z) + fabsf(mg1.w - g1.w);
        const bool hit = (bnd < 40.f) && (m != n);
        if (__any_sync(0xFFFFFFFFu, hit)) {
            const float4 v0 = *(const float4*)&sm[m][0];
            const float4 v1 = *(const float4*)&sm[m][4];
            const float4 v2 = *(const float4*)&sm[m][8];
            const float4 v3 = *(const float4*)&sm[m][12];
            float d = 0.f;
            d += fabsf(a0.x - v0.x); d += fabsf(a0.y - v0.y);
            d += fabsf(a0.z - v0.z); d += fabsf(a0.w - v0.w);
            d += fabsf(a1.x - v1.x); d += fabsf(a1.y - v1.y);
            d += fabsf(a1.z - v1.z); d += fabsf(a1.w - v1.w);
            d += fabsf(a2.x - v2.x); d += fabsf(a2.y - v2.y);
            d += fabsf(a2.z - v2.z); d += fabsf(a2.w - v2.w);
            d += fabsf(a3.x - v3.x); d += fabsf(a3.y - v3.y);
            d += fabsf(a3.z - v3.z); d += fabsf(a3.w - v3.w);
            if (m != n) acc += __expf(-d);
        }
    }

    if (q > 0) red[q - 1][nl] = acc;
    __syncthreads();
    if (q == 0)
        out[n * OUT_W + IN_F + b] =
            1.0f + acc + red[0][nl] + red[1][nl] + red[2][nl];
}

// ---------------------------------------------------------------------------
extern "C" void kernel_launch(void* const* d_in, const int* in_sizes, int n_in,
                              void* d_out, int out_size) {
    const float* x = (const float*)d_in[0];   // [256, 1024]
    const float* T = (const float*)d_in[1];   // [1024, 128, 16]
    float* out = (float*)d_out;               // [256, 1152]

    copy_kernel<<<256, 256>>>(x, out);
    gemm_fused_kernel<<<dim3(J_F / BN, N_SAMP / BM), 256>>>(x, T);
    pair_kernel<<<dim3(B_F, 2), 512>>>(out);
}